// round 14
// baseline (speedup 1.0000x reference)
#include <cuda_runtime.h>
#include <cuda_bf16.h>
#include <cuda_fp8.h>
#include <math.h>

#define Bsz 64
#define T 512
#define D 512
#define H 512
#define NG 2048  // 4*H
#define MTOT (Bsz*T)  // 32768

typedef unsigned long long u64;
typedef unsigned int u32;
typedef unsigned short u16;
typedef unsigned char u8;

// ---- common helpers ----
__device__ __forceinline__ u32 smem_u32(const void* p) {
    u32 a;
    asm("{ .reg .u64 t; cvta.to.shared.u64 t, %1; cvt.u32.u64 %0, t; }" : "=r"(a) : "l"(p));
    return a;
}
__device__ __forceinline__ void ldm4(u32* r, u32 p) {
    asm volatile("ldmatrix.sync.aligned.m8n8.x4.shared.b16 {%0,%1,%2,%3}, [%4];"
        : "=r"(r[0]), "=r"(r[1]), "=r"(r[2]), "=r"(r[3]) : "r"(p));
}
__device__ __forceinline__ void mma_bf16(float* d, const u32* a, u32 b0, u32 b1) {
    asm volatile("mma.sync.aligned.m16n8k16.row.col.f32.bf16.bf16.f32 "
        "{%0,%1,%2,%3}, {%4,%5,%6,%7}, {%8,%9}, {%0,%1,%2,%3};"
        : "+f"(d[0]), "+f"(d[1]), "+f"(d[2]), "+f"(d[3])
        : "r"(a[0]), "r"(a[1]), "r"(a[2]), "r"(a[3]), "r"(b0), "r"(b1));
}
// fp8 e4m3 mma, k32 (sm_89+ PTX feature; arch-generic, no tcgen05)
__device__ __forceinline__ void mma_e4m3(float* d, const u32* a, u32 b0, u32 b1) {
    asm volatile("mma.sync.aligned.m16n8k32.row.col.f32.e4m3.e4m3.f32 "
        "{%0,%1,%2,%3}, {%4,%5,%6,%7}, {%8,%9}, {%0,%1,%2,%3};"
        : "+f"(d[0]), "+f"(d[1]), "+f"(d[2]), "+f"(d[3])
        : "r"(a[0]), "r"(a[1]), "r"(a[2]), "r"(a[3]), "r"(b0), "r"(b1));
}
// pack two floats -> e4m3x2; e0 lands in the LOW byte
__device__ __forceinline__ u16 pack_e4m3_2(float e0, float e1) {
    u16 r;
    asm("cvt.rn.satfinite.e4m3x2.f32 %0, %1, %2;" : "=h"(r) : "f"(e1), "f"(e0));
    return r;
}
__device__ __forceinline__ u8 to_e4m3(float v) {
    return (u8)(pack_e4m3_2(v, 0.f) & 0xFF);
}
__device__ __forceinline__ float sigf(float x) {
    float e, r;
    asm("ex2.approx.f32 %0, %1;" : "=f"(e) : "f"(-x * 1.4426950408889634f));
    asm("rcp.approx.f32 %0, %1;" : "=f"(r) : "f"(1.0f + e));
    return r;
}
__device__ __forceinline__ float tanh_fast(float x) {
    return fmaf(2.f, sigf(2.f * x), -1.f);
}
__device__ __forceinline__ void red_release_add(unsigned* p, unsigned v) {
    asm volatile("red.release.gpu.global.add.u32 [%0], %1;" :: "l"(p), "r"(v) : "memory");
}
__device__ __forceinline__ unsigned ld_acquire(const unsigned* p) {
    unsigned v;
    asm volatile("ld.acquire.gpu.global.u32 %0, [%1];" : "=r"(v) : "l"(p) : "memory");
    return v;
}
#define CP16(dst, src) \
    asm volatile("cp.async.cg.shared.global [%0], [%1], 16;" :: "r"(dst), "l"(src))
#define CP_COMMIT asm volatile("cp.async.commit_group;")
#define BAR_SYNC(id, cnt) asm volatile("bar.sync %0, %1;" :: "r"(id), "r"(cnt) : "memory")

// ---- scratch ----
// Scales (exact powers of 2):
//   x_lo8 = e4m3((x - bf16(x)) * 2^5),  x_h8 = e4m3(x)        -> product scale 2^9
//   w_lo8 = e4m3((W - bf16(W)) * 2^9),  w_h8 = e4m3(W * 2^4)  -> shared with above
//   h_lo8 = e4m3((h - bf16(h)) * 2^9),  h_h8 = e4m3(h * 2^4)  -> product scale 2^13
__device__ float g_ZF[(size_t)T * Bsz * NG];
__device__ float g_ZB[(size_t)T * Bsz * NG];
__device__ __align__(16) __nv_bfloat16 g_hh[2][2][Bsz * H];
__device__ __align__(16) u8 g_hl8[2][2][Bsz * H];
__device__ __align__(16) u8 g_hh8[2][2][Bsz * H];
__device__ __align__(16) __nv_bfloat16 g_xh[(size_t)MTOT * D];
__device__ __align__(16) u8 g_xl8[(size_t)MTOT * D];
__device__ __align__(16) u8 g_xh8[(size_t)MTOT * D];
__device__ __align__(16) __nv_bfloat16 g_wth[2][(size_t)NG * 1024];
__device__ __align__(16) u8 g_wh8[2][(size_t)NG * 1024];
__device__ __align__(16) u8 g_wl8[2][(size_t)NG * 1024];
__device__ unsigned g_bar2[2][2];

__global__ void init_kernel() {
    int i = blockIdx.x * blockDim.x + threadIdx.x;
    if (i < Bsz * H) {
        __nv_bfloat16 z = __float2bfloat16(0.f);
        g_hh[0][0][i] = z; g_hh[0][1][i] = z; g_hh[1][0][i] = z; g_hh[1][1][i] = z;
        g_hl8[0][0][i] = 0; g_hl8[0][1][i] = 0; g_hl8[1][0][i] = 0; g_hl8[1][1][i] = 0;
        g_hh8[0][0][i] = 0; g_hh8[0][1][i] = 0; g_hh8[1][0][i] = 0; g_hh8[1][1][i] = 0;
    }
    if (i < 2) { g_bar2[i][0] = 0u; g_bar2[i][1] = 0u; }
}

__global__ void __launch_bounds__(256) split_x_kernel(const float* __restrict__ x) {
    int id = blockIdx.x * 256 + threadIdx.x;
    int m = id >> 6, c8 = id & 63;
    int b = m & (Bsz - 1), t = m >> 6;
    const float4* xp = (const float4*)(x + ((size_t)b * T + t) * D + c8 * 8);
    float4 v0 = xp[0], v1 = xp[1];
    float v[8] = {v0.x, v0.y, v0.z, v0.w, v1.x, v1.y, v1.z, v1.w};
    u16 hh[8]; float lo[8];
#pragma unroll
    for (int i = 0; i < 8; i++) {
        __nv_bfloat16 h = __float2bfloat16_rn(v[i]);
        hh[i] = __bfloat16_as_ushort(h);
        lo[i] = v[i] - __bfloat162float(h);
    }
    uint4 ph;
    ph.x = (u32)hh[0] | ((u32)hh[1] << 16); ph.y = (u32)hh[2] | ((u32)hh[3] << 16);
    ph.z = (u32)hh[4] | ((u32)hh[5] << 16); ph.w = (u32)hh[6] | ((u32)hh[7] << 16);
    *(uint4*)(g_xh + (size_t)m * D + c8 * 8) = ph;
    u16 l8[4], h8[4];
#pragma unroll
    for (int i = 0; i < 4; i++) {
        l8[i] = pack_e4m3_2(lo[2*i] * 32.f, lo[2*i+1] * 32.f);
        h8[i] = pack_e4m3_2(v[2*i], v[2*i+1]);
    }
    u64 pl8 = (u64)l8[0] | ((u64)l8[1] << 16) | ((u64)l8[2] << 32) | ((u64)l8[3] << 48);
    u64 ph8 = (u64)h8[0] | ((u64)h8[1] << 16) | ((u64)h8[2] << 32) | ((u64)h8[3] << 48);
    *(u64*)(g_xl8 + (size_t)m * D + c8 * 8) = pl8;
    *(u64*)(g_xh8 + (size_t)m * D + c8 * 8) = ph8;
}

__global__ void __launch_bounds__(256) split_w_kernel(
    const float* __restrict__ Wfw, const float* __restrict__ Wbw) {
    __shared__ float tile[32][33];
    int dir = blockIdx.z;
    int k0 = blockIdx.x * 32, n0 = blockIdx.y * 32;
    const float* W = dir ? Wbw : Wfw;
    int tid = threadIdx.x;
#pragma unroll
    for (int i = 0; i < 4; i++) {
        int idx = tid + i * 256;
        int r = idx >> 5, c = idx & 31;
        tile[r][c] = W[(size_t)(k0 + r) * NG + n0 + c];
    }
    __syncthreads();
#pragma unroll
    for (int i = 0; i < 4; i++) {
        int idx = tid + i * 256;
        int r = idx >> 5, c = idx & 31;
        float wv = tile[c][r];
        __nv_bfloat16 h = __float2bfloat16_rn(wv);
        float lo = wv - __bfloat162float(h);
        size_t o = (size_t)(n0 + r) * 1024 + k0 + c;
        g_wth[dir][o] = h;
        g_wh8[dir][o] = to_e4m3(wv * 16.f);
        g_wl8[dir][o] = to_e4m3(lo * 512.f);
    }
}

// ---------------------------------------------------------------------------
// Phase 1: Z = x @ W[:D] + b. Main term bf16 mma; corrections fp8 e4m3 k32.
// Buffer 64KB: xh 16K | Wh 16K | xl8 8K | xh8 8K | wh8 8K | wl8 8K. 3 stages.
// corr = (xl8*wh8 + xh8*wl8) * 2^-9 (shared scale -> one corr accumulator).
// ---------------------------------------------------------------------------
#define XH_O  0
#define WH_O  16384
#define XL8_O 32768
#define XH8_O 40960
#define WH8_O 49152
#define WL8_O 57344
#define G1_BUF 65536
#define G1_SMEM (3 * G1_BUF)

__global__ void __launch_bounds__(256, 1) gemm_x_mma(
    const float* __restrict__ bfw, const float* __restrict__ bbw)
{
    extern __shared__ char smem[];
    const u32 sb = smem_u32(smem);
    const int tid = threadIdx.x;
    const int wid = tid >> 5, lane = tid & 31;
    const int mw = wid & 3, nw = wid >> 2;
    const int l7 = lane & 7, sub = lane >> 3, gr = lane >> 2, tg = lane & 3;

    const int bm = blockIdx.y * 128;
    const int bn = blockIdx.x * 128;
    const int dir = bn >= 2048;
    const int n0 = bn - dir * 2048;
    const __nv_bfloat16* __restrict__ wth = g_wth[dir];
    const u8* __restrict__ wh8 = g_wh8[dir];
    const u8* __restrict__ wl8 = g_wl8[dir];

    const int rowA0 = mw * 32 + (sub & 1) * 8 + l7;
    const int rowA1 = rowA0 + 16;
    const int acbit = sub >> 1;
    const int rB0 = nw * 64 + ((sub & 2) ? 8 : 0) + l7;
    const int bcbit = sub & 1;

    float acc[2][8][4], accC[2][8][4];
#pragma unroll
    for (int i = 0; i < 2; i++)
#pragma unroll
        for (int j = 0; j < 8; j++)
#pragma unroll
            for (int e = 0; e < 4; e++) { acc[i][j][e] = 0.f; accC[i][j][e] = 0.f; }

    auto stage = [&](int kk, u32 base) {
#pragma unroll
        for (int j = 0; j < 4; j++) {
            int id = tid + j * 256;          // 0..1023
            int r = id >> 3, c = id & 7;
            u32 sw = (u32)((c ^ (r & 7)) << 4);
            CP16(base + XH_O + (u32)r * 128 + sw,
                 g_xh + (size_t)(bm + r) * D + kk * 64 + c * 8);
            CP16(base + WH_O + (u32)r * 128 + sw,
                 wth + (size_t)(n0 + r) * 1024 + kk * 64 + c * 8);
        }
#pragma unroll
        for (int j = 0; j < 4; j++) {
            int id = tid + j * 256;
            int arr = id >> 9, rem = id & 511;
            int r = rem >> 2, c = rem & 3;
            u32 sw = (u32)((c ^ (r & 3)) << 4);
            CP16(base + (arr ? XH8_O : XL8_O) + (u32)r * 64 + sw,
                 (arr ? g_xh8 : g_xl8) + (size_t)(bm + r) * D + kk * 64 + c * 16);
            CP16(base + (arr ? WL8_O : WH8_O) + (u32)r * 64 + sw,
                 (arr ? wl8 : wh8) + (size_t)(n0 + r) * 1024 + kk * 64 + c * 16);
        }
    };

    stage(0, sb);
    CP_COMMIT;
    stage(1, sb + G1_BUF);
    CP_COMMIT;

    for (int kk = 0; kk < 8; kk++) {
        u32 buf = sb + (u32)(kk % 3) * G1_BUF;
        if (kk < 7) { asm volatile("cp.async.wait_group 1;"); }
        else        { asm volatile("cp.async.wait_group 0;"); }
        __syncthreads();
        if (kk < 6) { stage(kk + 2, sb + (u32)((kk + 2) % 3) * G1_BUF); CP_COMMIT; }

        // main bf16
#pragma unroll
        for (int q = 0; q < 4; q++) {
            int ca = 2 * q + acbit;
            u32 a0[4], a1[4];
            ldm4(a0, buf + XH_O + (u32)rowA0 * 128 + (u32)((ca ^ (rowA0 & 7)) << 4));
            ldm4(a1, buf + XH_O + (u32)rowA1 * 128 + (u32)((ca ^ (rowA1 & 7)) << 4));
            int cb = 2 * q + bcbit;
#pragma unroll
            for (int j = 0; j < 4; j++) {
                int rB = rB0 + j * 16;
                u32 bh[4];
                ldm4(bh, buf + WH_O + (u32)rB * 128 + (u32)((cb ^ (rB & 7)) << 4));
                mma_bf16(acc[0][2*j],   a0, bh[0], bh[1]);
                mma_bf16(acc[0][2*j+1], a0, bh[2], bh[3]);
                mma_bf16(acc[1][2*j],   a1, bh[0], bh[1]);
                mma_bf16(acc[1][2*j+1], a1, bh[2], bh[3]);
            }
        }
        // fp8 corrections: 2 k32 chunk-pairs per kk
#pragma unroll
        for (int p = 0; p < 2; p++) {
            int cp = 2 * p + acbit;       // 0..3
            int cbp = 2 * p + bcbit;
            u32 aA0[4], aA1[4], aB0[4], aB1[4];
            ldm4(aA0, buf + XL8_O + (u32)rowA0 * 64 + (u32)((cp ^ (rowA0 & 3)) << 4));
            ldm4(aA1, buf + XL8_O + (u32)rowA1 * 64 + (u32)((cp ^ (rowA1 & 3)) << 4));
            ldm4(aB0, buf + XH8_O + (u32)rowA0 * 64 + (u32)((cp ^ (rowA0 & 3)) << 4));
            ldm4(aB1, buf + XH8_O + (u32)rowA1 * 64 + (u32)((cp ^ (rowA1 & 3)) << 4));
#pragma unroll
            for (int j = 0; j < 4; j++) {
                int nB = rB0 + j * 16;
                u32 bA[4], bB[4];
                ldm4(bA, buf + WH8_O + (u32)nB * 64 + (u32)((cbp ^ (nB & 3)) << 4));
                ldm4(bB, buf + WL8_O + (u32)nB * 64 + (u32)((cbp ^ (nB & 3)) << 4));
                mma_e4m3(accC[0][2*j],   aA0, bA[0], bA[1]);
                mma_e4m3(accC[0][2*j+1], aA0, bA[2], bA[3]);
                mma_e4m3(accC[1][2*j],   aA1, bA[0], bA[1]);
                mma_e4m3(accC[1][2*j+1], aA1, bA[2], bA[3]);
                mma_e4m3(accC[0][2*j],   aB0, bB[0], bB[1]);
                mma_e4m3(accC[0][2*j+1], aB0, bB[2], bB[3]);
                mma_e4m3(accC[1][2*j],   aB1, bB[0], bB[1]);
                mma_e4m3(accC[1][2*j+1], aB1, bB[2], bB[3]);
            }
        }
    }

    float* __restrict__ Zo = dir ? g_ZB : g_ZF;
    const float* __restrict__ bias = dir ? bbw : bfw;
    const float CS = 1.f / 512.f;     // 2^-9 shared correction scale
#pragma unroll
    for (int am = 0; am < 2; am++) {
        int m0 = bm + mw * 32 + am * 16 + gr;
#pragma unroll
        for (int p = 0; p < 8; p++) {
            int nc = n0 + nw * 64 + p * 8 + tg * 2;
            float bx = bias[nc], by = bias[nc + 1];
            const float* a = acc[am][p];
            const float* c = accC[am][p];
            *(float2*)(Zo + (size_t)m0 * NG + nc) =
                make_float2(fmaf(c[0], CS, a[0]) + bx, fmaf(c[1], CS, a[1]) + by);
            *(float2*)(Zo + (size_t)(m0 + 8) * NG + nc) =
                make_float2(fmaf(c[2], CS, a[2]) + bx, fmaf(c[3], CS, a[3]) + by);
        }
    }
}

// ---------------------------------------------------------------------------
// Phase 2: persistent kernel; main bf16 + fp8 corrections (shared scale 2^-13).
// SMEM: Ah 32K | h_lo8 16K | h_h8 16K | Bh 64K | W_h8 32K | W_lo8 32K | sP 2K.
// ---------------------------------------------------------------------------
#define A_OFF2  0
#define A8A_OFF 32768
#define A8B_OFF 49152
#define B_OFF2  65536
#define B8H_OFF 131072
#define B8L_OFF 163840
#define SP_OFF2 196608
#define P2_SMEM (SP_OFF2 + 2048 + 64)

__global__ void __launch_bounds__(256, 1) lstm_persistent(float* __restrict__ out)
{
    extern __shared__ char smem[];
    const u32 sb = smem_u32(smem);
    float* sP = (float*)(smem + SP_OFF2);

    const int dir   = blockIdx.x >> 6;
    const int rg    = (blockIdx.x >> 5) & 1;
    const int hTile = (blockIdx.x & 31) * 16;
    const float* __restrict__ Z = dir ? g_ZB : g_ZF;
    const __nv_bfloat16* __restrict__ wth = g_wth[dir];
    const u8* __restrict__ wh8p = g_wh8[dir];
    const u8* __restrict__ wl8p = g_wl8[dir];

    const int tid = threadIdx.x;
    const int wid = tid >> 5, lane = tid & 31;
    const int mw = wid & 1, q = wid >> 1;
    const int l7 = lane & 7, sub = lane >> 3;
    const int gr = lane >> 2, tg = lane & 3;

    const int arow = mw * 16 + ((sub & 1) ? 8 : 0) + l7;
    const int brow = q * 16 + ((sub & 2) ? 8 : 0) + l7;
    const u32 aRowBase  = sb + A_OFF2  + (u32)arow * 1024;
    const u32 a8aBase   = sb + A8A_OFF + (u32)arow * 512;
    const u32 a8bBase   = sb + A8B_OFF + (u32)arow * 512;
    const u32 bRowBase  = sb + B_OFF2  + (u32)brow * 1024;
    const u32 b8hBase   = sb + B8H_OFF + (u32)brow * 512;
    const u32 b8lBase   = sb + B8L_OFF + (u32)brow * 512;
    const int acbit = sub >> 1;
    const int bcbit = sub & 1;
    const int X = l7;

    // Stage resident B: Bh bf16 + W fp8 tiles
    for (int i = tid; i < 64 * 64; i += 256) {
        int n = i >> 6, kq = i & 63;
        int q16 = n >> 4, g2 = (n >> 3) & 1, hc8 = n & 7;
        int gate = (q16 & 1) * 2 + g2;
        int hcl = (q16 >> 1) * 8 + hc8;
        size_t ng = (size_t)(gate * H + hTile + hcl) * 1024 + 512 + (size_t)kq * 8;
        uint4 vh = *(const uint4*)(wth + ng);
        *(uint4*)(smem + B_OFF2 + n * 1024 + ((kq ^ (n & 7)) << 4)) = vh;
    }
    for (int i = tid; i < 64 * 32 * 2; i += 256) {
        int arr = i >> 11, rem = i & 2047;
        int n = rem >> 5, kq = rem & 31;
        int q16 = n >> 4, g2 = (n >> 3) & 1, hc8 = n & 7;
        int gate = (q16 & 1) * 2 + g2;
        int hcl = (q16 >> 1) * 8 + hc8;
        size_t ng = (size_t)(gate * H + hTile + hcl) * 1024 + 512 + (size_t)kq * 16;
        uint4 v = *(const uint4*)((arr ? wh8p : wl8p) + ng);
        *(uint4*)(smem + (arr ? B8H_OFF : B8L_OFF) + n * 512 + ((kq ^ (n & 7)) << 4)) = v;
    }
    __syncthreads();

    unsigned* bar = &g_bar2[dir][rg];
    const int R0 = mw * 16 + gr;
    const int hcl0 = (q >> 1) * 8 + tg * 2;
    const int nh = q & 1;
    const int g0 = nh * 2;
    const int hidx = (wid >> 1) * 32 + lane;
    const int halfbar = 1 + mw;
    const int pairbar = 3 + mw * 2 + (q >> 1);
    const float CS2 = 1.f / 8192.f;   // 2^-13

    float c0x = 0.f, c0y = 0.f, c1x = 0.f, c1y = 0.f;

    for (int s = 0; s < T; s++) {
        const int t = dir ? (T - 1 - s) : s;
        const int grow = rg * 32 + R0;

        const float* zp = Z + ((size_t)t * Bsz + grow) * NG + g0 * H + hTile + hcl0;
        float2 zA0 = __ldcg((const float2*)zp);
        float2 zB0 = __ldcg((const float2*)(zp + H));
        float2 zA1 = __ldcg((const float2*)(zp + 8 * NG));
        float2 zB1 = __ldcg((const float2*)(zp + 8 * NG + H));

        if (s > 0) {
            unsigned target = 128u * (unsigned)s;
            while (ld_acquire(bar) < target) { }
        }

        const __nv_bfloat16* hh  = g_hh[s & 1][dir]  + (rg * 32 + mw * 16) * H;
        const u8* hl8 = g_hl8[s & 1][dir] + (rg * 32 + mw * 16) * H;
        const u8* hh8 = g_hh8[s & 1][dir] + (rg * 32 + mw * 16) * H;

        // half 0: bf16 chunks 0-31 (k0-255) + fp8 chunks 0-15
#pragma unroll
        for (int j = 0; j < 4; j++) {
            int local = hidx + j * 128;
            int r = local >> 5, kq = local & 31;
            int rf = mw * 16 + r;
            CP16(sb + A_OFF2 + (u32)(rf * 1024 + ((kq ^ (rf & 7)) << 4)),
                 hh + r * 512 + kq * 8);
        }
#pragma unroll
        for (int j = 0; j < 4; j++) {
            int local = hidx + j * 128;
            int arr = local >> 8, rem = local & 255;
            int r = rem >> 4, kq = rem & 15;
            int rf = mw * 16 + r;
            CP16(sb + (arr ? A8B_OFF : A8A_OFF) + (u32)(rf * 512 + ((kq ^ (rf & 7)) << 4)),
                 (arr ? hh8 : hl8) + r * 512 + kq * 16);
        }
        CP_COMMIT;
        // half 1
#pragma unroll
        for (int j = 0; j < 4; j++) {
            int local = hidx + j * 128;
            int r = local >> 5, kq = 32 + (local & 31);
            int rf = mw * 16 + r;
            CP16(sb + A_OFF2 + (u32)(rf * 1024 + ((kq ^ (rf & 7)) << 4)),
                 hh + r * 512 + kq * 8);
        }
#pragma unroll
        for (int j = 0; j < 4; j++) {
            int local = hidx + j * 128;
            int arr = local >> 8, rem = local & 255;
            int r = rem >> 4, kq = 16 + (rem & 15);
            int rf = mw * 16 + r;
            CP16(sb + (arr ? A8B_OFF : A8A_OFF) + (u32)(rf * 512 + ((kq ^ (rf & 7)) << 4)),
                 (arr ? hh8 : hl8) + r * 512 + kq * 16);
        }
        CP_COMMIT;
        asm volatile("cp.async.wait_group 1;");
        BAR_SYNC(halfbar, 128);

        float d0m[4] = {0.f,0.f,0.f,0.f}, d1m[4] = {0.f,0.f,0.f,0.f};
        float d0a[4] = {0.f,0.f,0.f,0.f}, d1a[4] = {0.f,0.f,0.f,0.f};
        float d0b[4] = {0.f,0.f,0.f,0.f}, d1b[4] = {0.f,0.f,0.f,0.f};

#pragma unroll 8
        for (int kt = 0; kt < 16; kt++) {
            int ca = (kt << 1) | acbit;
            int cb = (kt << 1) | bcbit;
            u32 ah[4], bh[4];
            ldm4(ah, aRowBase + (u32)((ca ^ X) << 4));
            ldm4(bh, bRowBase + (u32)((cb ^ X) << 4));
            mma_bf16(d0m, ah, bh[0], bh[1]);
            mma_bf16(d1m, ah, bh[2], bh[3]);
        }
#pragma unroll 4
        for (int p = 0; p < 8; p++) {
            int cp = (p << 1) | acbit;
            int cbp = (p << 1) | bcbit;
            u32 aA[4], aB[4], bH[4], bL[4];
            ldm4(aA, a8aBase + (u32)((cp ^ X) << 4));
            ldm4(aB, a8bBase + (u32)((cp ^ X) << 4));
            ldm4(bH, b8hBase + (u32)((cbp ^ X) << 4));
            ldm4(bL, b8lBase + (u32)((cbp ^ X) << 4));
            mma_e4m3(d0a, aA, bH[0], bH[1]);
            mma_e4m3(d1a, aA, bH[2], bH[3]);
            mma_e4m3(d0b, aB, bL[0], bL[1]);
            mma_e4m3(d1b, aB, bL[2], bL[3]);
        }
        asm volatile("cp.async.wait_group 0;");
        BAR_SYNC(halfbar, 128);
#pragma unroll 8
        for (int kt = 16; kt < 32; kt++) {
            int ca = (kt << 1) | acbit;
            int cb = (kt << 1) | bcbit;
            u32 ah[4], bh[4];
            ldm4(ah, aRowBase + (u32)((ca ^ X) << 4));
            ldm4(bh, bRowBase + (u32)((cb ^ X) << 4));
            mma_bf16(d0m, ah, bh[0], bh[1]);
            mma_bf16(d1m, ah, bh[2], bh[3]);
        }
#pragma unroll 4
        for (int p = 8; p < 16; p++) {
            int cp = (p << 1) | acbit;
            int cbp = (p << 1) | bcbit;
            u32 aA[4], aB[4], bH[4], bL[4];
            ldm4(aA, a8aBase + (u32)((cp ^ X) << 4));
            ldm4(aB, a8bBase + (u32)((cp ^ X) << 4));
            ldm4(bH, b8hBase + (u32)((cbp ^ X) << 4));
            ldm4(bL, b8lBase + (u32)((cbp ^ X) << 4));
            mma_e4m3(d0a, aA, bH[0], bH[1]);
            mma_e4m3(d1a, aA, bH[2], bH[3]);
            mma_e4m3(d0b, aB, bL[0], bL[1]);
            mma_e4m3(d1b, aB, bL[2], bL[3]);
        }

        float d0[4], d1[4];
#pragma unroll
        for (int e = 0; e < 4; e++) {
            d0[e] = fmaf(d0a[e] + d0b[e], CS2, d0m[e]);
            d1[e] = fmaf(d1a[e] + d1b[e], CS2, d1m[e]);
        }

        if (nh == 0) {
            float2 p0, p1;
            p0.x = sigf(d0[0] + zA0.x) * tanh_fast(d1[0] + zB0.x);
            p0.y = sigf(d0[1] + zA0.y) * tanh_fast(d1[1] + zB0.y);
            p1.x = sigf(d0[2] + zA1.x) * tanh_fast(d1[2] + zB1.x);
            p1.y = sigf(d0[3] + zA1.y) * tanh_fast(d1[3] + zB1.y);
            *(float2*)&sP[R0 * 16 + hcl0]       = p0;
            *(float2*)&sP[(R0 + 8) * 16 + hcl0] = p1;
            BAR_SYNC(pairbar, 64);
        } else {
            float Fv[4], Ov[4];
            Fv[0] = sigf(d0[0] + zA0.x + 1.f); Fv[1] = sigf(d0[1] + zA0.y + 1.f);
            Fv[2] = sigf(d0[2] + zA1.x + 1.f); Fv[3] = sigf(d0[3] + zA1.y + 1.f);
            Ov[0] = sigf(d1[0] + zB0.x); Ov[1] = sigf(d1[1] + zB0.y);
            Ov[2] = sigf(d1[2] + zB1.x); Ov[3] = sigf(d1[3] + zB1.y);
            BAR_SYNC(pairbar, 64);

            float2 P0 = *(const float2*)&sP[R0 * 16 + hcl0];
            float2 P1 = *(const float2*)&sP[(R0 + 8) * 16 + hcl0];
            c0x = Fv[0] * c0x + P0.x; c0y = Fv[1] * c0y + P0.y;
            c1x = Fv[2] * c1x + P1.x; c1y = Fv[3] * c1y + P1.y;
            float h0x = Ov[0] * tanh_fast(c0x), h0y = Ov[1] * tanh_fast(c0y);
            float h1x = Ov[2] * tanh_fast(c1x), h1y = Ov[3] * tanh_fast(c1y);

            __nv_bfloat16 b0x = __float2bfloat16_rn(h0x), b0y = __float2bfloat16_rn(h0y);
            __nv_bfloat16 b1x = __float2bfloat16_rn(h1x), b1y = __float2bfloat16_rn(h1y);
            float l0x = h0x - __bfloat162float(b0x), l0y = h0y - __bfloat162float(b0y);
            float l1x = h1x - __bfloat162float(b1x), l1y = h1y - __bfloat162float(b1y);

            int pp = (s & 1) ^ 1;
            u32 o0 = (u32)(grow * H + hTile + hcl0);
            u32 o1 = o0 + 8 * H;
            *(u32*)&g_hh[pp][dir][o0] =
                (u32)__bfloat16_as_ushort(b0x) | ((u32)__bfloat16_as_ushort(b0y) << 16);
            *(u32*)&g_hh[pp][dir][o1] =
                (u32)__bfloat16_as_ushort(b1x) | ((u32)__bfloat16_as_ushort(b1y) << 16);
            *(u16*)&g_hl8[pp][dir][o0] = pack_e4m3_2(l0x * 512.f, l0y * 512.f);
            *(u16*)&g_hl8[pp][dir][o1] = pack_e4m3_2(l1x * 512.f, l1y * 512.f);
            *(u16*)&g_hh8[pp][dir][o0] = pack_e4m3_2(h0x * 16.f, h0y * 16.f);
            *(u16*)&g_hh8[pp][dir][o1] = pack_e4m3_2(h1x * 16.f, h1y * 16.f);

            __syncwarp();
            if (lane == 0) red_release_add(bar, 1u);

            *(float2*)(out + ((size_t)grow * T + t) * (2 * H) + dir * H + hTile + hcl0)
                = make_float2(h0x, h0y);
            *(float2*)(out + ((size_t)(grow + 8) * T + t) * (2 * H) + dir * H + hTile + hcl0)
                = make_float2(h1x, h1y);
        }
    }
}

extern "C" void kernel_launch(void* const* d_in, const int* in_sizes, int n_in,
                              void* d_out, int out_size) {
    const float* x    = (const float*)d_in[0];
    const float* W_fw = (const float*)d_in[1];
    const float* b_fw = (const float*)d_in[2];
    const float* W_bw = (const float*)d_in[3];
    const float* b_bw = (const float*)d_in[4];
    float* out = (float*)d_out;

    (void)in_sizes; (void)n_in; (void)out_size;

    cudaFuncSetAttribute(gemm_x_mma,
                         cudaFuncAttributeMaxDynamicSharedMemorySize, G1_SMEM);
    cudaFuncSetAttribute(lstm_persistent,
                         cudaFuncAttributeMaxDynamicSharedMemorySize, P2_SMEM);

    init_kernel<<<(Bsz * H + 255) / 256, 256>>>();
    split_x_kernel<<<MTOT * 64 / 256, 256>>>(x);
    split_w_kernel<<<dim3(32, 64, 2), 256>>>(W_fw, W_bw);

    gemm_x_mma<<<dim3(32, 256), 256, G1_SMEM>>>(b_fw, b_bw);

    lstm_persistent<<<128, 256, P2_SMEM>>>(out);
}

// round 15
// speedup vs baseline: 1.0164x; 1.0164x over previous
#include <cuda_runtime.h>
#include <cuda_bf16.h>
#include <cuda_fp8.h>
#include <math.h>

#define Bsz 64
#define T 512
#define D 512
#define H 512
#define NG 2048  // 4*H
#define MTOT (Bsz*T)  // 32768

typedef unsigned long long u64;
typedef unsigned int u32;
typedef unsigned short u16;
typedef unsigned char u8;

// ---- common helpers ----
__device__ __forceinline__ u32 smem_u32(const void* p) {
    u32 a;
    asm("{ .reg .u64 t; cvta.to.shared.u64 t, %1; cvt.u32.u64 %0, t; }" : "=r"(a) : "l"(p));
    return a;
}
__device__ __forceinline__ void ldm4(u32* r, u32 p) {
    asm volatile("ldmatrix.sync.aligned.m8n8.x4.shared.b16 {%0,%1,%2,%3}, [%4];"
        : "=r"(r[0]), "=r"(r[1]), "=r"(r[2]), "=r"(r[3]) : "r"(p));
}
__device__ __forceinline__ void mma_bf16(float* d, const u32* a, u32 b0, u32 b1) {
    asm volatile("mma.sync.aligned.m16n8k16.row.col.f32.bf16.bf16.f32 "
        "{%0,%1,%2,%3}, {%4,%5,%6,%7}, {%8,%9}, {%0,%1,%2,%3};"
        : "+f"(d[0]), "+f"(d[1]), "+f"(d[2]), "+f"(d[3])
        : "r"(a[0]), "r"(a[1]), "r"(a[2]), "r"(a[3]), "r"(b0), "r"(b1));
}
__device__ __forceinline__ void mma_e4m3(float* d, const u32* a, u32 b0, u32 b1) {
    asm volatile("mma.sync.aligned.m16n8k32.row.col.f32.e4m3.e4m3.f32 "
        "{%0,%1,%2,%3}, {%4,%5,%6,%7}, {%8,%9}, {%0,%1,%2,%3};"
        : "+f"(d[0]), "+f"(d[1]), "+f"(d[2]), "+f"(d[3])
        : "r"(a[0]), "r"(a[1]), "r"(a[2]), "r"(a[3]), "r"(b0), "r"(b1));
}
__device__ __forceinline__ u16 pack_e4m3_2(float e0, float e1) {
    u16 r;
    asm("cvt.rn.satfinite.e4m3x2.f32 %0, %1, %2;" : "=h"(r) : "f"(e1), "f"(e0));
    return r;
}
__device__ __forceinline__ u8 to_e4m3(float v) {
    return (u8)(pack_e4m3_2(v, 0.f) & 0xFF);
}
__device__ __forceinline__ void split_bf16(float x, u16& hb, u16& lb) {
    __nv_bfloat16 h = __float2bfloat16_rn(x);
    hb = __bfloat16_as_ushort(h);
    lb = __bfloat16_as_ushort(__float2bfloat16_rn(x - __bfloat162float(h)));
}
__device__ __forceinline__ float sigf(float x) {
    float e, r;
    asm("ex2.approx.f32 %0, %1;" : "=f"(e) : "f"(-x * 1.4426950408889634f));
    asm("rcp.approx.f32 %0, %1;" : "=f"(r) : "f"(1.0f + e));
    return r;
}
__device__ __forceinline__ float tanh_fast(float x) {
    return fmaf(2.f, sigf(2.f * x), -1.f);
}
__device__ __forceinline__ void red_release_add(unsigned* p, unsigned v) {
    asm volatile("red.release.gpu.global.add.u32 [%0], %1;" :: "l"(p), "r"(v) : "memory");
}
__device__ __forceinline__ unsigned ld_acquire(const unsigned* p) {
    unsigned v;
    asm volatile("ld.acquire.gpu.global.u32 %0, [%1];" : "=r"(v) : "l"(p) : "memory");
    return v;
}
#define CP16(dst, src) \
    asm volatile("cp.async.cg.shared.global [%0], [%1], 16;" :: "r"(dst), "l"(src))
#define CP_COMMIT asm volatile("cp.async.commit_group;")
#define BAR_SYNC(id, cnt) asm volatile("bar.sync %0, %1;" :: "r"(id), "r"(cnt) : "memory")

// ---- scratch ----
// fp8 scales (powers of 2): xl8 = e4m3(x_lo*2^5), xh8 = e4m3(x),
// wh8 = e4m3(W*2^4), wl8 = e4m3(W_lo*2^9) -> both corr products at 2^9.
__device__ float g_ZF[(size_t)T * Bsz * NG];
__device__ float g_ZB[(size_t)T * Bsz * NG];
__device__ __align__(16) __nv_bfloat16 g_hh[2][2][Bsz * H];
__device__ __align__(16) __nv_bfloat16 g_hl[2][2][Bsz * H];
__device__ __align__(16) __nv_bfloat16 g_xh[(size_t)MTOT * D];
__device__ __align__(16) u8 g_xl8[(size_t)MTOT * D];
__device__ __align__(16) u8 g_xh8[(size_t)MTOT * D];
__device__ __align__(16) __nv_bfloat16 g_wth[2][(size_t)NG * 1024];
__device__ __align__(16) __nv_bfloat16 g_wtl[2][(size_t)NG * 1024];
__device__ __align__(16) u8 g_wh8[2][(size_t)NG * 1024];
__device__ __align__(16) u8 g_wl8[2][(size_t)NG * 1024];
__device__ unsigned g_bar2[2][2];

__global__ void init_kernel() {
    int i = blockIdx.x * blockDim.x + threadIdx.x;
    if (i < Bsz * H) {
        __nv_bfloat16 z = __float2bfloat16(0.f);
        g_hh[0][0][i] = z; g_hh[0][1][i] = z; g_hh[1][0][i] = z; g_hh[1][1][i] = z;
        g_hl[0][0][i] = z; g_hl[0][1][i] = z; g_hl[1][0][i] = z; g_hl[1][1][i] = z;
    }
    if (i < 2) { g_bar2[i][0] = 0u; g_bar2[i][1] = 0u; }
}

__global__ void __launch_bounds__(256) split_x_kernel(const float* __restrict__ x) {
    int id = blockIdx.x * 256 + threadIdx.x;
    int m = id >> 6, c8 = id & 63;
    int b = m & (Bsz - 1), t = m >> 6;
    const float4* xp = (const float4*)(x + ((size_t)b * T + t) * D + c8 * 8);
    float4 v0 = xp[0], v1 = xp[1];
    float v[8] = {v0.x, v0.y, v0.z, v0.w, v1.x, v1.y, v1.z, v1.w};
    u16 hh[8]; float lo[8];
#pragma unroll
    for (int i = 0; i < 8; i++) {
        __nv_bfloat16 h = __float2bfloat16_rn(v[i]);
        hh[i] = __bfloat16_as_ushort(h);
        lo[i] = v[i] - __bfloat162float(h);
    }
    uint4 ph;
    ph.x = (u32)hh[0] | ((u32)hh[1] << 16); ph.y = (u32)hh[2] | ((u32)hh[3] << 16);
    ph.z = (u32)hh[4] | ((u32)hh[5] << 16); ph.w = (u32)hh[6] | ((u32)hh[7] << 16);
    *(uint4*)(g_xh + (size_t)m * D + c8 * 8) = ph;
    u16 l8[4], h8[4];
#pragma unroll
    for (int i = 0; i < 4; i++) {
        l8[i] = pack_e4m3_2(lo[2*i] * 32.f, lo[2*i+1] * 32.f);
        h8[i] = pack_e4m3_2(v[2*i], v[2*i+1]);
    }
    u64 pl8 = (u64)l8[0] | ((u64)l8[1] << 16) | ((u64)l8[2] << 32) | ((u64)l8[3] << 48);
    u64 ph8 = (u64)h8[0] | ((u64)h8[1] << 16) | ((u64)h8[2] << 32) | ((u64)h8[3] << 48);
    *(u64*)(g_xl8 + (size_t)m * D + c8 * 8) = pl8;
    *(u64*)(g_xh8 + (size_t)m * D + c8 * 8) = ph8;
}

__global__ void __launch_bounds__(256) split_w_kernel(
    const float* __restrict__ Wfw, const float* __restrict__ Wbw) {
    __shared__ float tile[32][33];
    int dir = blockIdx.z;
    int k0 = blockIdx.x * 32, n0 = blockIdx.y * 32;
    const float* W = dir ? Wbw : Wfw;
    int tid = threadIdx.x;
#pragma unroll
    for (int i = 0; i < 4; i++) {
        int idx = tid + i * 256;
        int r = idx >> 5, c = idx & 31;
        tile[r][c] = W[(size_t)(k0 + r) * NG + n0 + c];
    }
    __syncthreads();
#pragma unroll
    for (int i = 0; i < 4; i++) {
        int idx = tid + i * 256;
        int r = idx >> 5, c = idx & 31;
        float wv = tile[c][r];
        __nv_bfloat16 h = __float2bfloat16_rn(wv);
        float lo = wv - __bfloat162float(h);
        size_t o = (size_t)(n0 + r) * 1024 + k0 + c;
        g_wth[dir][o] = h;
        g_wtl[dir][o] = __float2bfloat16_rn(lo);
        g_wh8[dir][o] = to_e4m3(wv * 16.f);
        g_wl8[dir][o] = to_e4m3(lo * 512.f);
    }
}

// ---------------------------------------------------------------------------
// Phase 1 v3: 128x64 tile, main bf16 + fp8 e4m3 corrections.
// Buffer 48KB: xh 16K | Wh 8K | xl8 8K | xh8 8K | wh8 4K | wl8 4K. 3 stages.
// 8 warps = 4 mw (m32) x 2 nw (n32); per warp m32 x n32.
// corr = (xl8*wh8 + xh8*wl8) * 2^-9.
// ---------------------------------------------------------------------------
#define XH_O  0
#define WH_O  16384
#define XL8_O 24576
#define XH8_O 32768
#define WH8_O 40960
#define WL8_O 45056
#define G1_BUF 49152
#define G1_SMEM (3 * G1_BUF)

__global__ void __launch_bounds__(256, 1) gemm_x_mma(
    const float* __restrict__ bfw, const float* __restrict__ bbw)
{
    extern __shared__ char smem[];
    const u32 sb = smem_u32(smem);
    const int tid = threadIdx.x;
    const int wid = tid >> 5, lane = tid & 31;
    const int mw = wid & 3, nw = wid >> 2;
    const int l7 = lane & 7, sub = lane >> 3, gr = lane >> 2, tg = lane & 3;

    const int bm = blockIdx.y * 128;
    const int bn = blockIdx.x * 64;
    const int dir = bn >= 2048;
    const int n0 = bn - dir * 2048;
    const __nv_bfloat16* __restrict__ wth = g_wth[dir];
    const u8* __restrict__ wh8 = g_wh8[dir];
    const u8* __restrict__ wl8 = g_wl8[dir];

    const int rowA0 = mw * 32 + (sub & 1) * 8 + l7;
    const int rowA1 = rowA0 + 16;
    const int acbit = sub >> 1;
    const int rB0 = nw * 32 + ((sub & 2) ? 8 : 0) + l7;
    const int bcbit = sub & 1;

    float acc[2][4][4], accC[2][4][4];
#pragma unroll
    for (int i = 0; i < 2; i++)
#pragma unroll
        for (int j = 0; j < 4; j++)
#pragma unroll
            for (int e = 0; e < 4; e++) { acc[i][j][e] = 0.f; accC[i][j][e] = 0.f; }

    auto stage = [&](int kk, u32 base) {
#pragma unroll
        for (int j = 0; j < 4; j++) {            // A hi: 1024 cp
            int id = tid + j * 256;
            int r = id >> 3, c = id & 7;
            CP16(base + XH_O + (u32)(r * 128 + ((c ^ (r & 7)) << 4)),
                 g_xh + (size_t)(bm + r) * D + kk * 64 + c * 8);
        }
#pragma unroll
        for (int j = 0; j < 2; j++) {            // B hi: 512 cp
            int id = tid + j * 256;
            int r = id >> 3, c = id & 7;
            CP16(base + WH_O + (u32)(r * 128 + ((c ^ (r & 7)) << 4)),
                 wth + (size_t)(n0 + r) * 1024 + kk * 64 + c * 8);
        }
#pragma unroll
        for (int j = 0; j < 4; j++) {            // x fp8: 1024 cp
            int id = tid + j * 256;
            int arr = id >> 9, rem = id & 511;
            int r = rem >> 2, c = rem & 3;
            CP16(base + (arr ? XH8_O : XL8_O) + (u32)(r * 64 + ((c ^ (r & 3)) << 4)),
                 (arr ? g_xh8 : g_xl8) + (size_t)(bm + r) * D + kk * 64 + c * 16);
        }
#pragma unroll
        for (int j = 0; j < 2; j++) {            // W fp8: 512 cp
            int id = tid + j * 256;
            int arr = id >> 8, rem = id & 255;
            int r = rem >> 2, c = rem & 3;
            CP16(base + (arr ? WL8_O : WH8_O) + (u32)(r * 64 + ((c ^ (r & 3)) << 4)),
                 (arr ? wl8 : wh8) + (size_t)(n0 + r) * 1024 + kk * 64 + c * 16);
        }
    };

    stage(0, sb);
    CP_COMMIT;
    stage(1, sb + G1_BUF);
    CP_COMMIT;

    for (int kk = 0; kk < 8; kk++) {
        u32 buf = sb + (u32)(kk % 3) * G1_BUF;
        if (kk < 7) { asm volatile("cp.async.wait_group 1;"); }
        else        { asm volatile("cp.async.wait_group 0;"); }
        __syncthreads();
        if (kk < 6) { stage(kk + 2, sb + (u32)((kk + 2) % 3) * G1_BUF); CP_COMMIT; }

        // main bf16: 32 mma
#pragma unroll
        for (int q = 0; q < 4; q++) {
            int ca = 2 * q + acbit;
            u32 a0[4], a1[4];
            ldm4(a0, buf + XH_O + (u32)(rowA0 * 128 + ((ca ^ (rowA0 & 7)) << 4)));
            ldm4(a1, buf + XH_O + (u32)(rowA1 * 128 + ((ca ^ (rowA1 & 7)) << 4)));
            int cb = 2 * q + bcbit;
#pragma unroll
            for (int j = 0; j < 2; j++) {
                int rB = rB0 + j * 16;
                u32 bh[4];
                ldm4(bh, buf + WH_O + (u32)(rB * 128 + ((cb ^ (rB & 7)) << 4)));
                mma_bf16(acc[0][2*j],   a0, bh[0], bh[1]);
                mma_bf16(acc[0][2*j+1], a0, bh[2], bh[3]);
                mma_bf16(acc[1][2*j],   a1, bh[0], bh[1]);
                mma_bf16(acc[1][2*j+1], a1, bh[2], bh[3]);
            }
        }
        // fp8 corrections: 32 mma (k32)
#pragma unroll
        for (int p = 0; p < 2; p++) {
            int cp = 2 * p + acbit;
            int cbp = 2 * p + bcbit;
            u32 aA0[4], aA1[4], aB0[4], aB1[4];
            ldm4(aA0, buf + XL8_O + (u32)(rowA0 * 64 + ((cp ^ (rowA0 & 3)) << 4)));
            ldm4(aA1, buf + XL8_O + (u32)(rowA1 * 64 + ((cp ^ (rowA1 & 3)) << 4)));
            ldm4(aB0, buf + XH8_O + (u32)(rowA0 * 64 + ((cp ^ (rowA0 & 3)) << 4)));
            ldm4(aB1, buf + XH8_O + (u32)(rowA1 * 64 + ((cp ^ (rowA1 & 3)) << 4)));
#pragma unroll
            for (int j = 0; j < 2; j++) {
                int rB = rB0 + j * 16;
                u32 bA[4], bB[4];
                ldm4(bA, buf + WH8_O + (u32)(rB * 64 + ((cbp ^ (rB & 3)) << 4)));
                ldm4(bB, buf + WL8_O + (u32)(rB * 64 + ((cbp ^ (rB & 3)) << 4)));
                mma_e4m3(accC[0][2*j],   aA0, bA[0], bA[1]);
                mma_e4m3(accC[0][2*j+1], aA0, bA[2], bA[3]);
                mma_e4m3(accC[1][2*j],   aA1, bA[0], bA[1]);
                mma_e4m3(accC[1][2*j+1], aA1, bA[2], bA[3]);
                mma_e4m3(accC[0][2*j],   aB0, bB[0], bB[1]);
                mma_e4m3(accC[0][2*j+1], aB0, bB[2], bB[3]);
                mma_e4m3(accC[1][2*j],   aB1, bB[0], bB[1]);
                mma_e4m3(accC[1][2*j+1], aB1, bB[2], bB[3]);
            }
        }
    }

    float* __restrict__ Zo = dir ? g_ZB : g_ZF;
    const float* __restrict__ bias = dir ? bbw : bfw;
    const float CS = 1.f / 512.f;     // 2^-9
#pragma unroll
    for (int am = 0; am < 2; am++) {
        int m0 = bm + mw * 32 + am * 16 + gr;
#pragma unroll
        for (int p = 0; p < 4; p++) {
            int nc = n0 + nw * 32 + p * 8 + tg * 2;
            float bx = bias[nc], by = bias[nc + 1];
            const float* a = acc[am][p];
            const float* c = accC[am][p];
            *(float2*)(Zo + (size_t)m0 * NG + nc) =
                make_float2(fmaf(c[0], CS, a[0]) + bx, fmaf(c[1], CS, a[1]) + by);
            *(float2*)(Zo + (size_t)(m0 + 8) * NG + nc) =
                make_float2(fmaf(c[2], CS, a[2]) + bx, fmaf(c[3], CS, a[3]) + by);
        }
    }
}

// ---------------------------------------------------------------------------
// Phase 2: EXACT R13 kernel (best measured) — bf16 3-term, per-term accums.
// ---------------------------------------------------------------------------
#define A_OFF2 0
#define B_OFF2 65536
#define SP_OFF2 (B_OFF2 + 131072)
#define P2_SMEM (SP_OFF2 + 2048 + 64)

__global__ void __launch_bounds__(256, 1) lstm_persistent(float* __restrict__ out)
{
    extern __shared__ char smem[];
    const u32 sb = smem_u32(smem);
    float* sP = (float*)(smem + SP_OFF2);

    const int dir   = blockIdx.x >> 6;
    const int rg    = (blockIdx.x >> 5) & 1;
    const int hTile = (blockIdx.x & 31) * 16;
    const float* __restrict__ Z = dir ? g_ZB : g_ZF;
    const __nv_bfloat16* __restrict__ wth = g_wth[dir];
    const __nv_bfloat16* __restrict__ wtl = g_wtl[dir];

    const int tid = threadIdx.x;
    const int wid = tid >> 5, lane = tid & 31;
    const int mw = wid & 1, q = wid >> 1;
    const int l7 = lane & 7, sub = lane >> 3;
    const int gr = lane >> 2, tg = lane & 3;

    const u32 aRowBase = sb + A_OFF2 + (u32)(mw * 16 + ((sub & 1) ? 8 : 0) + l7) * 2048;
    const int acbit = sub >> 1;
    const u32 bRowBase = sb + B_OFF2 + (u32)(q * 16 + ((sub & 2) ? 8 : 0) + l7) * 2048;
    const int bcbit = sub & 1;
    const int X = l7;

    for (int i = tid; i < 64 * 64; i += 256) {
        int n = i >> 6, kq = i & 63;
        int q16 = n >> 4, g2 = (n >> 3) & 1, hc8 = n & 7;
        int gate = (q16 & 1) * 2 + g2;
        int hcl = (q16 >> 1) * 8 + hc8;
        size_t ng = (size_t)(gate * H + hTile + hcl) * 1024 + 512 + kq * 8;
        uint4 vh = *(const uint4*)(wth + ng);
        uint4 vl = *(const uint4*)(wtl + ng);
        u32 dst = (u32)(n * 2048 + ((kq ^ (n & 7)) << 4));
        *(uint4*)(smem + B_OFF2 + dst)        = vh;
        *(uint4*)(smem + B_OFF2 + dst + 1024) = vl;
    }
    __syncthreads();

    unsigned* bar = &g_bar2[dir][rg];
    const int R0 = mw * 16 + gr;
    const int hcl0 = (q >> 1) * 8 + tg * 2;
    const int nh = q & 1;
    const int g0 = nh * 2;
    const int hidx = (wid >> 1) * 32 + lane;
    const int halfbar = 1 + mw;
    const int pairbar = 3 + mw * 2 + (q >> 1);

    float c0x = 0.f, c0y = 0.f, c1x = 0.f, c1y = 0.f;

    for (int s = 0; s < T; s++) {
        const int t = dir ? (T - 1 - s) : s;
        const int grow = rg * 32 + R0;

        const float* zp = Z + ((size_t)t * Bsz + grow) * NG + g0 * H + hTile + hcl0;
        float2 zA0 = __ldcg((const float2*)zp);
        float2 zB0 = __ldcg((const float2*)(zp + H));
        float2 zA1 = __ldcg((const float2*)(zp + 8 * NG));
        float2 zB1 = __ldcg((const float2*)(zp + 8 * NG + H));

        if (s > 0) {
            unsigned target = 128u * (unsigned)s;
            while (ld_acquire(bar) < target) { }
        }

        const __nv_bfloat16* hh = g_hh[s & 1][dir] + (rg * 32 + mw * 16) * H;
        const __nv_bfloat16* hl = g_hl[s & 1][dir] + (rg * 32 + mw * 16) * H;
#pragma unroll
        for (int j = 0; j < 4; j++) {
            int local = hidx + j * 128;
            int r = local >> 5, kq = local & 31;
            int rfull = mw * 16 + r;
            u32 dst = sb + A_OFF2 + (u32)(rfull * 2048 + ((kq ^ (rfull & 7)) << 4));
            CP16(dst,        hh + r * 512 + kq * 8);
            CP16(dst + 1024, hl + r * 512 + kq * 8);
        }
        CP_COMMIT;
#pragma unroll
        for (int j = 0; j < 4; j++) {
            int local = hidx + j * 128;
            int r = local >> 5, kq = 32 + (local & 31);
            int rfull = mw * 16 + r;
            u32 dst = sb + A_OFF2 + (u32)(rfull * 2048 + ((kq ^ (rfull & 7)) << 4));
            CP16(dst,        hh + r * 512 + kq * 8);
            CP16(dst + 1024, hl + r * 512 + kq * 8);
        }
        CP_COMMIT;
        asm volatile("cp.async.wait_group 1;");
        BAR_SYNC(halfbar, 128);

        float d0h[4] = {0.f,0.f,0.f,0.f}, d1h[4] = {0.f,0.f,0.f,0.f};
        float d0a[4] = {0.f,0.f,0.f,0.f}, d1a[4] = {0.f,0.f,0.f,0.f};
        float d0b[4] = {0.f,0.f,0.f,0.f}, d1b[4] = {0.f,0.f,0.f,0.f};
#pragma unroll 8
        for (int kt = 0; kt < 16; kt++) {
            int ca = (kt << 1) | acbit;
            int cb = (kt << 1) | bcbit;
            u32 ah[4], al[4], bh[4], bl[4];
            ldm4(ah, aRowBase + (u32)((ca ^ X) << 4));
            ldm4(al, aRowBase + (u32)(((ca + 64) ^ X) << 4));
            ldm4(bh, bRowBase + (u32)((cb ^ X) << 4));
            ldm4(bl, bRowBase + (u32)(((cb + 64) ^ X) << 4));
            mma_bf16(d0h, ah, bh[0], bh[1]);
            mma_bf16(d1h, ah, bh[2], bh[3]);
            mma_bf16(d0a, al, bh[0], bh[1]);
            mma_bf16(d1a, al, bh[2], bh[3]);
            mma_bf16(d0b, ah, bl[0], bl[1]);
            mma_bf16(d1b, ah, bl[2], bl[3]);
        }
        asm volatile("cp.async.wait_group 0;");
        BAR_SYNC(halfbar, 128);
#pragma unroll 8
        for (int kt = 16; kt < 32; kt++) {
            int ca = (kt << 1) | acbit;
            int cb = (kt << 1) | bcbit;
            u32 ah[4], al[4], bh[4], bl[4];
            ldm4(ah, aRowBase + (u32)((ca ^ X) << 4));
            ldm4(al, aRowBase + (u32)(((ca + 64) ^ X) << 4));
            ldm4(bh, bRowBase + (u32)((cb ^ X) << 4));
            ldm4(bl, bRowBase + (u32)(((cb + 64) ^ X) << 4));
            mma_bf16(d0h, ah, bh[0], bh[1]);
            mma_bf16(d1h, ah, bh[2], bh[3]);
            mma_bf16(d0a, al, bh[0], bh[1]);
            mma_bf16(d1a, al, bh[2], bh[3]);
            mma_bf16(d0b, ah, bl[0], bl[1]);
            mma_bf16(d1b, ah, bl[2], bl[3]);
        }

        float d0[4], d1[4];
#pragma unroll
        for (int e = 0; e < 4; e++) {
            d0[e] = d0h[e] + d0a[e] + d0b[e];
            d1[e] = d1h[e] + d1a[e] + d1b[e];
        }

        if (nh == 0) {
            float2 p0, p1;
            p0.x = sigf(d0[0] + zA0.x) * tanh_fast(d1[0] + zB0.x);
            p0.y = sigf(d0[1] + zA0.y) * tanh_fast(d1[1] + zB0.y);
            p1.x = sigf(d0[2] + zA1.x) * tanh_fast(d1[2] + zB1.x);
            p1.y = sigf(d0[3] + zA1.y) * tanh_fast(d1[3] + zB1.y);
            *(float2*)&sP[R0 * 16 + hcl0]       = p0;
            *(float2*)&sP[(R0 + 8) * 16 + hcl0] = p1;
            BAR_SYNC(pairbar, 64);
        } else {
            float Fv[4], Ov[4];
            Fv[0] = sigf(d0[0] + zA0.x + 1.f); Fv[1] = sigf(d0[1] + zA0.y + 1.f);
            Fv[2] = sigf(d0[2] + zA1.x + 1.f); Fv[3] = sigf(d0[3] + zA1.y + 1.f);
            Ov[0] = sigf(d1[0] + zB0.x); Ov[1] = sigf(d1[1] + zB0.y);
            Ov[2] = sigf(d1[2] + zB1.x); Ov[3] = sigf(d1[3] + zB1.y);
            BAR_SYNC(pairbar, 64);

            float2 P0 = *(const float2*)&sP[R0 * 16 + hcl0];
            float2 P1 = *(const float2*)&sP[(R0 + 8) * 16 + hcl0];
            c0x = Fv[0] * c0x + P0.x; c0y = Fv[1] * c0y + P0.y;
            c1x = Fv[2] * c1x + P1.x; c1y = Fv[3] * c1y + P1.y;
            float h0x = Ov[0] * tanh_fast(c0x), h0y = Ov[1] * tanh_fast(c0y);
            float h1x = Ov[2] * tanh_fast(c1x), h1y = Ov[3] * tanh_fast(c1y);

            u16 ha0, la0, ha1, la1, hb0, lb0, hb1, lb1;
            split_bf16(h0x, ha0, la0); split_bf16(h0y, ha1, la1);
            split_bf16(h1x, hb0, lb0); split_bf16(h1y, hb1, lb1);
            int pp = (s & 1) ^ 1;
            u32 o0 = (u32)(grow * H + hTile + hcl0);
            u32 o1 = o0 + 8 * H;
            *(u32*)&g_hh[pp][dir][o0] = (u32)ha0 | ((u32)ha1 << 16);
            *(u32*)&g_hl[pp][dir][o0] = (u32)la0 | ((u32)la1 << 16);
            *(u32*)&g_hh[pp][dir][o1] = (u32)hb0 | ((u32)hb1 << 16);
            *(u32*)&g_hl[pp][dir][o1] = (u32)lb0 | ((u32)lb1 << 16);

            __syncwarp();
            if (lane == 0) red_release_add(bar, 1u);

            *(float2*)(out + ((size_t)grow * T + t) * (2 * H) + dir * H + hTile + hcl0)
                = make_float2(h0x, h0y);
            *(float2*)(out + ((size_t)(grow + 8) * T + t) * (2 * H) + dir * H + hTile + hcl0)
                = make_float2(h1x, h1y);
        }
    }
}

extern "C" void kernel_launch(void* const* d_in, const int* in_sizes, int n_in,
                              void* d_out, int out_size) {
    const float* x    = (const float*)d_in[0];
    const float* W_fw = (const float*)d_in[1];
    const float* b_fw = (const float*)d_in[2];
    const float* W_bw = (const float*)d_in[3];
    const float* b_bw = (const float*)d_in[4];
    float* out = (float*)d_out;

    (void)in_sizes; (void)n_in; (void)out_size;

    cudaFuncSetAttribute(gemm_x_mma,
                         cudaFuncAttributeMaxDynamicSharedMemorySize, G1_SMEM);
    cudaFuncSetAttribute(lstm_persistent,
                         cudaFuncAttributeMaxDynamicSharedMemorySize, P2_SMEM);

    init_kernel<<<(Bsz * H + 255) / 256, 256>>>();
    split_x_kernel<<<MTOT * 64 / 256, 256>>>(x);
    split_w_kernel<<<dim3(32, 64, 2), 256>>>(W_fw, W_bw);

    gemm_x_mma<<<dim3(64, 256), 256, G1_SMEM>>>(b_fw, b_bw);

    lstm_persistent<<<128, 256, P2_SMEM>>>(out);
}

// round 16
// speedup vs baseline: 1.1342x; 1.1159x over previous
#include <cuda_runtime.h>
#include <cuda_bf16.h>
#include <math.h>

#define Bsz 64
#define T 512
#define D 512
#define H 512
#define NG 2048  // 4*H
#define MTOT (Bsz*T)  // 32768

typedef unsigned long long u64;
typedef unsigned int u32;
typedef unsigned short u16;

// ---- common helpers ----
__device__ __forceinline__ u32 smem_u32(const void* p) {
    u32 a;
    asm("{ .reg .u64 t; cvta.to.shared.u64 t, %1; cvt.u32.u64 %0, t; }" : "=r"(a) : "l"(p));
    return a;
}
__device__ __forceinline__ void ldm4(u32* r, u32 p) {
    asm volatile("ldmatrix.sync.aligned.m8n8.x4.shared.b16 {%0,%1,%2,%3}, [%4];"
        : "=r"(r[0]), "=r"(r[1]), "=r"(r[2]), "=r"(r[3]) : "r"(p));
}
__device__ __forceinline__ void mma_bf16(float* d, const u32* a, u32 b0, u32 b1) {
    asm volatile("mma.sync.aligned.m16n8k16.row.col.f32.bf16.bf16.f32 "
        "{%0,%1,%2,%3}, {%4,%5,%6,%7}, {%8,%9}, {%0,%1,%2,%3};"
        : "+f"(d[0]), "+f"(d[1]), "+f"(d[2]), "+f"(d[3])
        : "r"(a[0]), "r"(a[1]), "r"(a[2]), "r"(a[3]), "r"(b0), "r"(b1));
}
__device__ __forceinline__ void split_bf16(float x, u16& hb, u16& lb) {
    __nv_bfloat16 h = __float2bfloat16_rn(x);
    hb = __bfloat16_as_ushort(h);
    lb = __bfloat16_as_ushort(__float2bfloat16_rn(x - __bfloat162float(h)));
}
__device__ __forceinline__ float sigf(float x) {
    float e, r;
    asm("ex2.approx.f32 %0, %1;" : "=f"(e) : "f"(-x * 1.4426950408889634f));
    asm("rcp.approx.f32 %0, %1;" : "=f"(r) : "f"(1.0f + e));
    return r;
}
__device__ __forceinline__ float tanh_fast(float x) {
    return fmaf(2.f, sigf(2.f * x), -1.f);
}
__device__ __forceinline__ void red_release_add(unsigned* p, unsigned v) {
    asm volatile("red.release.gpu.global.add.u32 [%0], %1;" :: "l"(p), "r"(v) : "memory");
}
__device__ __forceinline__ unsigned ld_acquire(const unsigned* p) {
    unsigned v;
    asm volatile("ld.acquire.gpu.global.u32 %0, [%1];" : "=r"(v) : "l"(p) : "memory");
    return v;
}
#define CP16(dst, src) \
    asm volatile("cp.async.cg.shared.global [%0], [%1], 16;" :: "r"(dst), "l"(src))
#define CP_COMMIT asm volatile("cp.async.commit_group;")
#define BAR_SYNC(id, cnt) asm volatile("bar.sync %0, %1;" :: "r"(id), "r"(cnt) : "memory")

// ---- scratch ----
__device__ float g_ZF[(size_t)T * Bsz * NG];
__device__ float g_ZB[(size_t)T * Bsz * NG];
__device__ __align__(16) __nv_bfloat16 g_hh[2][2][Bsz * H];
__device__ __align__(16) __nv_bfloat16 g_hl[2][2][Bsz * H];
__device__ __align__(16) __nv_bfloat16 g_xh[(size_t)MTOT * D];   // row m = t*B + b
__device__ __align__(16) __nv_bfloat16 g_xl[(size_t)MTOT * D];
__device__ __align__(16) __nv_bfloat16 g_wth[2][(size_t)NG * 1024]; // [dir][n][k]
__device__ __align__(16) __nv_bfloat16 g_wtl[2][(size_t)NG * 1024];
__device__ unsigned g_bar2[2][2];      // [dir][rg]

__global__ void init_kernel() {
    int i = blockIdx.x * blockDim.x + threadIdx.x;
    if (i < Bsz * H) {
        __nv_bfloat16 z = __float2bfloat16(0.f);
        g_hh[0][0][i] = z; g_hh[0][1][i] = z; g_hh[1][0][i] = z; g_hh[1][1][i] = z;
        g_hl[0][0][i] = z; g_hl[0][1][i] = z; g_hl[1][0][i] = z; g_hl[1][1][i] = z;
    }
    if (i < 2) { g_bar2[i][0] = 0u; g_bar2[i][1] = 0u; }
}

__global__ void __launch_bounds__(256) split_x_kernel(const float* __restrict__ x) {
    int id = blockIdx.x * 256 + threadIdx.x;
    int m = id >> 6, c8 = id & 63;
    int b = m & (Bsz - 1), t = m >> 6;
    const float4* xp = (const float4*)(x + ((size_t)b * T + t) * D + c8 * 8);
    float4 v0 = xp[0], v1 = xp[1];
    u16 h[8], l[8];
    split_bf16(v0.x, h[0], l[0]); split_bf16(v0.y, h[1], l[1]);
    split_bf16(v0.z, h[2], l[2]); split_bf16(v0.w, h[3], l[3]);
    split_bf16(v1.x, h[4], l[4]); split_bf16(v1.y, h[5], l[5]);
    split_bf16(v1.z, h[6], l[6]); split_bf16(v1.w, h[7], l[7]);
    uint4 ph, pl;
    ph.x = (u32)h[0] | ((u32)h[1] << 16); ph.y = (u32)h[2] | ((u32)h[3] << 16);
    ph.z = (u32)h[4] | ((u32)h[5] << 16); ph.w = (u32)h[6] | ((u32)h[7] << 16);
    pl.x = (u32)l[0] | ((u32)l[1] << 16); pl.y = (u32)l[2] | ((u32)l[3] << 16);
    pl.z = (u32)l[4] | ((u32)l[5] << 16); pl.w = (u32)l[6] | ((u32)l[7] << 16);
    *(uint4*)(g_xh + (size_t)m * D + c8 * 8) = ph;
    *(uint4*)(g_xl + (size_t)m * D + c8 * 8) = pl;
}

__global__ void __launch_bounds__(256) split_w_kernel(
    const float* __restrict__ Wfw, const float* __restrict__ Wbw) {
    __shared__ float tile[32][33];
    int dir = blockIdx.z;
    int k0 = blockIdx.x * 32, n0 = blockIdx.y * 32;
    const float* W = dir ? Wbw : Wfw;
    int tid = threadIdx.x;
#pragma unroll
    for (int i = 0; i < 4; i++) {
        int idx = tid + i * 256;
        int r = idx >> 5, c = idx & 31;
        tile[r][c] = W[(size_t)(k0 + r) * NG + n0 + c];
    }
    __syncthreads();
#pragma unroll
    for (int i = 0; i < 4; i++) {
        int idx = tid + i * 256;
        int r = idx >> 5, c = idx & 31;
        u16 hb, lb; split_bf16(tile[c][r], hb, lb);
        size_t o = (size_t)(n0 + r) * 1024 + k0 + c;
        g_wth[dir][o] = __ushort_as_bfloat16(hb);
        g_wtl[dir][o] = __ushort_as_bfloat16(lb);
    }
}

// ---------------------------------------------------------------------------
// Phase 1 v4: 128x128 tile, BK=32, 3-stage x 32KB buffers -> 96KB smem,
// __launch_bounds__(256,2) => 2 CTAs/SM co-resident to hide pipeline gaps.
// Buffer: Ah 8K | Al 8K | Bh 8K | Bl 8K (rows 64B, XOR swizzle over 4 chunks).
// ---------------------------------------------------------------------------
#define G1_BUF 32768
#define G1_SMEM (3 * G1_BUF)

__global__ void __launch_bounds__(256, 2) gemm_x_mma(
    const float* __restrict__ bfw, const float* __restrict__ bbw)
{
    extern __shared__ char smem[];
    const u32 sb = smem_u32(smem);
    const int tid = threadIdx.x;
    const int wid = tid >> 5, lane = tid & 31;
    const int mw = wid & 3, nw = wid >> 2;
    const int l7 = lane & 7, sub = lane >> 3, gr = lane >> 2, tg = lane & 3;

    const int bm = blockIdx.y * 128;
    const int bn = blockIdx.x * 128;
    const int dir = bn >= 2048;
    const int n0 = bn - dir * 2048;
    const __nv_bfloat16* __restrict__ wth = g_wth[dir];
    const __nv_bfloat16* __restrict__ wtl = g_wtl[dir];

    const int rowA0 = mw * 32 + (sub & 1) * 8 + l7;
    const int rowA1 = rowA0 + 16;
    const int acbit = sub >> 1;
    const int rB0 = nw * 64 + ((sub & 2) ? 8 : 0) + l7;
    const int bcbit = sub & 1;

    float acc[2][8][4];
#pragma unroll
    for (int i = 0; i < 2; i++)
#pragma unroll
        for (int j = 0; j < 8; j++)
#pragma unroll
            for (int q = 0; q < 4; q++) acc[i][j][q] = 0.f;

    // stage one BK=32 chunk (2048 x 16B total; 8 cp/thread)
    auto stage = [&](int kk, u32 base) {
#pragma unroll
        for (int j = 0; j < 2; j++) {
            int id = tid + j * 256;              // 0..511
            int r = id >> 2, c = id & 3;
            u32 sw = (u32)(r * 64 + ((c ^ (r & 3)) << 4));
            size_t ao = (size_t)(bm + r) * D + kk * 32 + c * 8;
            CP16(base + sw,         g_xh + ao);
            CP16(base + 8192 + sw,  g_xl + ao);
            size_t bo = (size_t)(n0 + r) * 1024 + kk * 32 + c * 8;
            CP16(base + 16384 + sw, wth + bo);
            CP16(base + 24576 + sw, wtl + bo);
        }
    };

    stage(0, sb);
    CP_COMMIT;
    stage(1, sb + G1_BUF);
    CP_COMMIT;

    for (int kk = 0; kk < 16; kk++) {
        u32 buf = sb + (u32)(kk % 3) * G1_BUF;
        if (kk < 15) { asm volatile("cp.async.wait_group 1;"); }
        else         { asm volatile("cp.async.wait_group 0;"); }
        __syncthreads();
        if (kk < 14) { stage(kk + 2, sb + (u32)((kk + 2) % 3) * G1_BUF); CP_COMMIT; }
#pragma unroll
        for (int q = 0; q < 2; q++) {
            int ca = 2 * q + acbit;              // 0..3
            u32 a0[4], a1[4], al0[4], al1[4];
            u32 aoff0 = (u32)(rowA0 * 64 + ((ca ^ (rowA0 & 3)) << 4));
            u32 aoff1 = (u32)(rowA1 * 64 + ((ca ^ (rowA1 & 3)) << 4));
            ldm4(a0,  buf + aoff0);
            ldm4(a1,  buf + aoff1);
            ldm4(al0, buf + 8192 + aoff0);
            ldm4(al1, buf + 8192 + aoff1);
            int cb = 2 * q + bcbit;
#pragma unroll
            for (int j = 0; j < 4; j++) {
                int rB = rB0 + j * 16;
                u32 boff = (u32)(rB * 64 + ((cb ^ (rB & 3)) << 4));
                u32 bh[4], bl[4];
                ldm4(bh, buf + 16384 + boff);
                ldm4(bl, buf + 24576 + boff);
                mma_bf16(acc[0][2*j],   a0,  bh[0], bh[1]);
                mma_bf16(acc[0][2*j+1], a0,  bh[2], bh[3]);
                mma_bf16(acc[1][2*j],   a1,  bh[0], bh[1]);
                mma_bf16(acc[1][2*j+1], a1,  bh[2], bh[3]);
                mma_bf16(acc[0][2*j],   al0, bh[0], bh[1]);
                mma_bf16(acc[0][2*j+1], al0, bh[2], bh[3]);
                mma_bf16(acc[1][2*j],   al1, bh[0], bh[1]);
                mma_bf16(acc[1][2*j+1], al1, bh[2], bh[3]);
                mma_bf16(acc[0][2*j],   a0,  bl[0], bl[1]);
                mma_bf16(acc[0][2*j+1], a0,  bl[2], bl[3]);
                mma_bf16(acc[1][2*j],   a1,  bl[0], bl[1]);
                mma_bf16(acc[1][2*j+1], a1,  bl[2], bl[3]);
            }
        }
    }

    float* __restrict__ Zo = dir ? g_ZB : g_ZF;
    const float* __restrict__ bias = dir ? bbw : bfw;
#pragma unroll
    for (int am = 0; am < 2; am++) {
        int m0 = bm + mw * 32 + am * 16 + gr;
#pragma unroll
        for (int p = 0; p < 8; p++) {
            int nc = n0 + nw * 64 + p * 8 + tg * 2;
            float bx = bias[nc], by = bias[nc + 1];
            const float* a = acc[am][p];
            *(float2*)(Zo + (size_t)m0 * NG + nc)       = make_float2(a[0] + bx, a[1] + by);
            *(float2*)(Zo + (size_t)(m0 + 8) * NG + nc) = make_float2(a[2] + bx, a[3] + by);
        }
    }
}

// ---------------------------------------------------------------------------
// Phase 2: EXACT R13 kernel (best measured).
// ---------------------------------------------------------------------------
#define A_OFF2 0
#define B_OFF2 65536
#define SP_OFF2 (B_OFF2 + 131072)
#define P2_SMEM (SP_OFF2 + 2048 + 64)

__global__ void __launch_bounds__(256, 1) lstm_persistent(float* __restrict__ out)
{
    extern __shared__ char smem[];
    const u32 sb = smem_u32(smem);
    float* sP = (float*)(smem + SP_OFF2);

    const int dir   = blockIdx.x >> 6;
    const int rg    = (blockIdx.x >> 5) & 1;
    const int hTile = (blockIdx.x & 31) * 16;
    const float* __restrict__ Z = dir ? g_ZB : g_ZF;
    const __nv_bfloat16* __restrict__ wth = g_wth[dir];
    const __nv_bfloat16* __restrict__ wtl = g_wtl[dir];

    const int tid = threadIdx.x;
    const int wid = tid >> 5, lane = tid & 31;
    const int mw = wid & 1, q = wid >> 1;
    const int l7 = lane & 7, sub = lane >> 3;
    const int gr = lane >> 2, tg = lane & 3;

    const u32 aRowBase = sb + A_OFF2 + (u32)(mw * 16 + ((sub & 1) ? 8 : 0) + l7) * 2048;
    const int acbit = sub >> 1;
    const u32 bRowBase = sb + B_OFF2 + (u32)(q * 16 + ((sub & 2) ? 8 : 0) + l7) * 2048;
    const int bcbit = sub & 1;
    const int X = l7;

    for (int i = tid; i < 64 * 64; i += 256) {
        int n = i >> 6, kq = i & 63;
        int q16 = n >> 4, g2 = (n >> 3) & 1, hc8 = n & 7;
        int gate = (q16 & 1) * 2 + g2;
        int hcl = (q16 >> 1) * 8 + hc8;
        size_t ng = (size_t)(gate * H + hTile + hcl) * 1024 + 512 + kq * 8;
        uint4 vh = *(const uint4*)(wth + ng);
        uint4 vl = *(const uint4*)(wtl + ng);
        u32 dst = (u32)(n * 2048 + ((kq ^ (n & 7)) << 4));
        *(uint4*)(smem + B_OFF2 + dst)        = vh;
        *(uint4*)(smem + B_OFF2 + dst + 1024) = vl;
    }
    __syncthreads();

    unsigned* bar = &g_bar2[dir][rg];
    const int R0 = mw * 16 + gr;
    const int hcl0 = (q >> 1) * 8 + tg * 2;
    const int nh = q & 1;
    const int g0 = nh * 2;
    const int hidx = (wid >> 1) * 32 + lane;
    const int halfbar = 1 + mw;
    const int pairbar = 3 + mw * 2 + (q >> 1);

    float c0x = 0.f, c0y = 0.f, c1x = 0.f, c1y = 0.f;

    for (int s = 0; s < T; s++) {
        const int t = dir ? (T - 1 - s) : s;
        const int grow = rg * 32 + R0;

        const float* zp = Z + ((size_t)t * Bsz + grow) * NG + g0 * H + hTile + hcl0;
        float2 zA0 = __ldcg((const float2*)zp);
        float2 zB0 = __ldcg((const float2*)(zp + H));
        float2 zA1 = __ldcg((const float2*)(zp + 8 * NG));
        float2 zB1 = __ldcg((const float2*)(zp + 8 * NG + H));

        if (s > 0) {
            unsigned target = 128u * (unsigned)s;
            while (ld_acquire(bar) < target) { }
        }

        const __nv_bfloat16* hh = g_hh[s & 1][dir] + (rg * 32 + mw * 16) * H;
        const __nv_bfloat16* hl = g_hl[s & 1][dir] + (rg * 32 + mw * 16) * H;
#pragma unroll
        for (int j = 0; j < 4; j++) {
            int local = hidx + j * 128;
            int r = local >> 5, kq = local & 31;
            int rfull = mw * 16 + r;
            u32 dst = sb + A_OFF2 + (u32)(rfull * 2048 + ((kq ^ (rfull & 7)) << 4));
            CP16(dst,        hh + r * 512 + kq * 8);
            CP16(dst + 1024, hl + r * 512 + kq * 8);
        }
        CP_COMMIT;
#pragma unroll
        for (int j = 0; j < 4; j++) {
            int local = hidx + j * 128;
            int r = local >> 5, kq = 32 + (local & 31);
            int rfull = mw * 16 + r;
            u32 dst = sb + A_OFF2 + (u32)(rfull * 2048 + ((kq ^ (rfull & 7)) << 4));
            CP16(dst,        hh + r * 512 + kq * 8);
            CP16(dst + 1024, hl + r * 512 + kq * 8);
        }
        CP_COMMIT;
        asm volatile("cp.async.wait_group 1;");
        BAR_SYNC(halfbar, 128);

        float d0h[4] = {0.f,0.f,0.f,0.f}, d1h[4] = {0.f,0.f,0.f,0.f};
        float d0a[4] = {0.f,0.f,0.f,0.f}, d1a[4] = {0.f,0.f,0.f,0.f};
        float d0b[4] = {0.f,0.f,0.f,0.f}, d1b[4] = {0.f,0.f,0.f,0.f};
#pragma unroll 8
        for (int kt = 0; kt < 16; kt++) {
            int ca = (kt << 1) | acbit;
            int cb = (kt << 1) | bcbit;
            u32 ah[4], al[4], bh[4], bl[4];
            ldm4(ah, aRowBase + (u32)((ca ^ X) << 4));
            ldm4(al, aRowBase + (u32)(((ca + 64) ^ X) << 4));
            ldm4(bh, bRowBase + (u32)((cb ^ X) << 4));
            ldm4(bl, bRowBase + (u32)(((cb + 64) ^ X) << 4));
            mma_bf16(d0h, ah, bh[0], bh[1]);
            mma_bf16(d1h, ah, bh[2], bh[3]);
            mma_bf16(d0a, al, bh[0], bh[1]);
            mma_bf16(d1a, al, bh[2], bh[3]);
            mma_bf16(d0b, ah, bl[0], bl[1]);
            mma_bf16(d1b, ah, bl[2], bl[3]);
        }
        asm volatile("cp.async.wait_group 0;");
        BAR_SYNC(halfbar, 128);
#pragma unroll 8
        for (int kt = 16; kt < 32; kt++) {
            int ca = (kt << 1) | acbit;
            int cb = (kt << 1) | bcbit;
            u32 ah[4], al[4], bh[4], bl[4];
            ldm4(ah, aRowBase + (u32)((ca ^ X) << 4));
            ldm4(al, aRowBase + (u32)(((ca + 64) ^ X) << 4));
            ldm4(bh, bRowBase + (u32)((cb ^ X) << 4));
            ldm4(bl, bRowBase + (u32)(((cb + 64) ^ X) << 4));
            mma_bf16(d0h, ah, bh[0], bh[1]);
            mma_bf16(d1h, ah, bh[2], bh[3]);
            mma_bf16(d0a, al, bh[0], bh[1]);
            mma_bf16(d1a, al, bh[2], bh[3]);
            mma_bf16(d0b, ah, bl[0], bl[1]);
            mma_bf16(d1b, ah, bl[2], bl[3]);
        }

        float d0[4], d1[4];
#pragma unroll
        for (int e = 0; e < 4; e++) {
            d0[e] = d0h[e] + d0a[e] + d0b[e];
            d1[e] = d1h[e] + d1a[e] + d1b[e];
        }

        if (nh == 0) {
            float2 p0, p1;
            p0.x = sigf(d0[0] + zA0.x) * tanh_fast(d1[0] + zB0.x);
            p0.y = sigf(d0[1] + zA0.y) * tanh_fast(d1[1] + zB0.y);
            p1.x = sigf(d0[2] + zA1.x) * tanh_fast(d1[2] + zB1.x);
            p1.y = sigf(d0[3] + zA1.y) * tanh_fast(d1[3] + zB1.y);
            *(float2*)&sP[R0 * 16 + hcl0]       = p0;
            *(float2*)&sP[(R0 + 8) * 16 + hcl0] = p1;
            BAR_SYNC(pairbar, 64);
        } else {
            float Fv[4], Ov[4];
            Fv[0] = sigf(d0[0] + zA0.x + 1.f); Fv[1] = sigf(d0[1] + zA0.y + 1.f);
            Fv[2] = sigf(d0[2] + zA1.x + 1.f); Fv[3] = sigf(d0[3] + zA1.y + 1.f);
            Ov[0] = sigf(d1[0] + zB0.x); Ov[1] = sigf(d1[1] + zB0.y);
            Ov[2] = sigf(d1[2] + zB1.x); Ov[3] = sigf(d1[3] + zB1.y);
            BAR_SYNC(pairbar, 64);

            float2 P0 = *(const float2*)&sP[R0 * 16 + hcl0];
            float2 P1 = *(const float2*)&sP[(R0 + 8) * 16 + hcl0];
            c0x = Fv[0] * c0x + P0.x; c0y = Fv[1] * c0y + P0.y;
            c1x = Fv[2] * c1x + P1.x; c1y = Fv[3] * c1y + P1.y;
            float h0x = Ov[0] * tanh_fast(c0x), h0y = Ov[1] * tanh_fast(c0y);
            float h1x = Ov[2] * tanh_fast(c1x), h1y = Ov[3] * tanh_fast(c1y);

            u16 ha0, la0, ha1, la1, hb0, lb0, hb1, lb1;
            split_bf16(h0x, ha0, la0); split_bf16(h0y, ha1, la1);
            split_bf16(h1x, hb0, lb0); split_bf16(h1y, hb1, lb1);
            int pp = (s & 1) ^ 1;
            u32 o0 = (u32)(grow * H + hTile + hcl0);
            u32 o1 = o0 + 8 * H;
            *(u32*)&g_hh[pp][dir][o0] = (u32)ha0 | ((u32)ha1 << 16);
            *(u32*)&g_hl[pp][dir][o0] = (u32)la0 | ((u32)la1 << 16);
            *(u32*)&g_hh[pp][dir][o1] = (u32)hb0 | ((u32)hb1 << 16);
            *(u32*)&g_hl[pp][dir][o1] = (u32)lb0 | ((u32)lb1 << 16);

            __syncwarp();
            if (lane == 0) red_release_add(bar, 1u);

            *(float2*)(out + ((size_t)grow * T + t) * (2 * H) + dir * H + hTile + hcl0)
                = make_float2(h0x, h0y);
            *(float2*)(out + ((size_t)(grow + 8) * T + t) * (2 * H) + dir * H + hTile + hcl0)
                = make_float2(h1x, h1y);
        }
    }
}

extern "C" void kernel_launch(void* const* d_in, const int* in_sizes, int n_in,
                              void* d_out, int out_size) {
    const float* x    = (const float*)d_in[0];
    const float* W_fw = (const float*)d_in[1];
    const float* b_fw = (const float*)d_in[2];
    const float* W_bw = (const float*)d_in[3];
    const float* b_bw = (const float*)d_in[4];
    float* out = (float*)d_out;

    (void)in_sizes; (void)n_in; (void)out_size;

    cudaFuncSetAttribute(gemm_x_mma,
                         cudaFuncAttributeMaxDynamicSharedMemorySize, G1_SMEM);
    cudaFuncSetAttribute(lstm_persistent,
                         cudaFuncAttributeMaxDynamicSharedMemorySize, P2_SMEM);

    init_kernel<<<(Bsz * H + 255) / 256, 256>>>();
    split_x_kernel<<<MTOT * 64 / 256, 256>>>(x);
    split_w_kernel<<<dim3(32, 64, 2), 256>>>(W_fw, W_bw);

    gemm_x_mma<<<dim3(32, 256), 256, G1_SMEM>>>(b_fw, b_bw);

    lstm_persistent<<<128, 256, P2_SMEM>>>(out);
}